// round 7
// baseline (speedup 1.0000x reference)
#include <cuda_runtime.h>
#include <math.h>

#define HW   (128*128)
#define CHW  (16*HW)
typedef unsigned long long ull;

// ---------------- scratch ----------------
__device__ float g_b1[7*CHW];    // conv1 out (3) / conv3 out (7)
__device__ float g_b2[5*CHW];    // conv2 out (5) -- kept for final skip recompute
__device__ float g_b3[9*CHW];    // conv4 out (9)
__device__ float g_sum[4*16];
__device__ float g_sumsq[4*16];

struct Taps { int isl[9][3]; int msk[9][3]; float mult[9]; };

// ---------------- f32x2 helpers ----------------
__device__ __forceinline__ ull pack2(float v){
    ull r; asm("mov.b64 %0,{%1,%2};" : "=l"(r) : "f"(v), "f"(v)); return r;
}
__device__ __forceinline__ void fma2(ull &d, ull a, ull b){
    asm("fma.rn.f32x2 %0,%1,%2,%0;" : "+l"(d) : "l"(a), "l"(b));
}
__device__ __forceinline__ void unpack2(ull a, float &x, float &y){
    asm("mov.b64 {%0,%1},%2;" : "=f"(x), "=f"(y) : "l"(a));
}

// ---------------- fused conv stage ----------------
// MODE 0: raw input. MODE 1: relu(fma(x,a,b)), a=istd, b=-mean*istd finalized
// inline from raw atomic sums. MODE 2: relu(fma(x,a,b) + skip).
// Halo: transform applies ONLY to in-range pixels; out-of-range pad is 0.
// Block: 256 threads (16 z x 16 y), thread = 1 px x 16 co (8 f32x2 accs).
// Tile 16x16, grid x = 64 tiles, y = output slice.
template<int MODE>
__global__ __launch_bounds__(256) void conv_stage(
    const float* __restrict__ in, size_t in_stride,
    float* __restrict__ out,
    const float* __restrict__ w, const float* __restrict__ bias,
    const float* __restrict__ prev_s, const float* __restrict__ prev_q,
    const float* __restrict__ skip,
    float* __restrict__ stat_s, float* __restrict__ stat_q,
    Taps tp)
{
    __shared__ float s_w[16*9*16];      // [ci][k][co], mask-summed over kx
    __shared__ float s_in[16*18*18];    // [ci][r][c]
    __shared__ float s_a[16], s_b[16];
    __shared__ float s_red[8][32];

    const int osl = blockIdx.y;
    const int tile = blockIdx.x;
    const int tz0 = (tile >> 3) << 4;
    const int ty0 = (tile &  7) << 4;
    const int tid = threadIdx.x;
    const int tz  = tid >> 4;          // 0..15
    const int ty  = tid & 15;          // 0..15

    // inline finalize of previous stage's instance-norm stats
    if (MODE > 0 && tid < 16){
        double sd = (double)prev_s[tid];
        double qd = (double)prev_q[tid];
        double mean = sd / 2097152.0;
        double var  = qd / 2097152.0 - mean*mean;
        double isd  = 1.0 / sqrt(var + 1e-5);
        s_a[tid] = (float)isd;
        s_b[tid] = (float)(-mean*isd);
    }

    // tile-load slots: slot0 = tid (always < 324), slot1 = tid+256 (tid < 68)
    int px0, px1; bool ok0, ok1;
    {
        int r = tid/18, c = tid - r*18;
        int gz = tz0 + r - 1, gy = ty0 + c - 1;
        ok0 = ((unsigned)gz < 128u) && ((unsigned)gy < 128u);
        px0 = gz*128 + gy;
        int j = tid + 256;
        r = j/18; c = j - r*18;
        gz = tz0 + r - 1; gy = ty0 + c - 1;
        ok1 = (j < 324) && ((unsigned)gz < 128u) && ((unsigned)gy < 128u);
        px1 = gz*128 + gy;
    }

    ull acc[8];
#pragma unroll
    for (int t=0;t<8;t++) acc[t] = 0ull;

    for (int e=0; e<3; e++){
        const int isl = tp.isl[osl][e];
        if (isl < 0) continue;
        const int m = tp.msk[osl][e];
        __syncthreads();
        // weights (summed over kx taps sharing this input slice)
#pragma unroll
        for (int it=0; it<9; it++){
            int idx = tid + it*256;
            int co = idx & 15;
            int k  = (idx >> 4) % 9;
            int ci = idx / 144;
            int base = ((co*16+ci)*9 + k)*3;
            float wv = 0.f;
            if (m & 1) wv += w[base+0];
            if (m & 2) wv += w[base+1];
            if (m & 4) wv += w[base+2];
            s_w[idx] = wv;
        }
        // input tile: slot-major, all 16 ci LDGs batched (MLP 16/32).
        // Transform only valid pixels; out-of-range = 0 (conv zero-pad).
        const float* ip = in + (size_t)isl*in_stride;
        {
            float xv[16];
#pragma unroll
            for (int ci=0; ci<16; ci++)
                xv[ci] = ok0 ? ip[ci*HW + px0] : 0.f;
            if (MODE == 2){
                float sv[16];
#pragma unroll
                for (int ci=0; ci<16; ci++)
                    sv[ci] = ok0 ? skip[ci*HW + px0] : 0.f;
#pragma unroll
                for (int ci=0; ci<16; ci++){
                    float t = fmaxf(fmaf(xv[ci], s_a[ci], s_b[ci]) + sv[ci], 0.f);
                    s_in[ci*324 + tid] = ok0 ? t : 0.f;
                }
            } else if (MODE == 1){
#pragma unroll
                for (int ci=0; ci<16; ci++){
                    float t = fmaxf(fmaf(xv[ci], s_a[ci], s_b[ci]), 0.f);
                    s_in[ci*324 + tid] = ok0 ? t : 0.f;
                }
            } else {
#pragma unroll
                for (int ci=0; ci<16; ci++)
                    s_in[ci*324 + tid] = xv[ci];
            }
            if (tid < 68){
                float yv[16];
#pragma unroll
                for (int ci=0; ci<16; ci++)
                    yv[ci] = ok1 ? ip[ci*HW + px1] : 0.f;
                if (MODE == 2){
                    float sv[16];
#pragma unroll
                    for (int ci=0; ci<16; ci++)
                        sv[ci] = ok1 ? skip[ci*HW + px1] : 0.f;
#pragma unroll
                    for (int ci=0; ci<16; ci++){
                        float t = fmaxf(fmaf(yv[ci], s_a[ci], s_b[ci]) + sv[ci], 0.f);
                        s_in[ci*324 + tid + 256] = ok1 ? t : 0.f;
                    }
                } else if (MODE == 1){
#pragma unroll
                    for (int ci=0; ci<16; ci++){
                        float t = fmaxf(fmaf(yv[ci], s_a[ci], s_b[ci]), 0.f);
                        s_in[ci*324 + tid + 256] = ok1 ? t : 0.f;
                    }
                } else {
#pragma unroll
                    for (int ci=0; ci<16; ci++)
                        s_in[ci*324 + tid + 256] = yv[ci];
                }
            }
        }
        __syncthreads();

        // compute: 1 px x 16 co
        const float* sbase = s_in + tz*18 + ty;
#pragma unroll 1
        for (int ci=0; ci<16; ci++){
            const float* si = sbase + ci*324;
            ull p[3][3];
#pragma unroll
            for (int r=0; r<3; r++)
#pragma unroll
                for (int c=0; c<3; c++)
                    p[r][c] = pack2(si[r*18 + c]);
            const float* wbase = s_w + ci*144;
#pragma unroll
            for (int k=0; k<9; k++){
                const ulonglong2* wq = reinterpret_cast<const ulonglong2*>(wbase + k*16);
                ulonglong2 wa = wq[0], wb = wq[1];
                ull pv = p[k/3][k%3];
                fma2(acc[0],pv,wa.x); fma2(acc[1],pv,wa.y);
                fma2(acc[2],pv,wb.x); fma2(acc[3],pv,wb.y);
                wa = wq[2]; wb = wq[3];
                fma2(acc[4],pv,wa.x); fma2(acc[5],pv,wa.y);
                fma2(acc[6],pv,wb.x); fma2(acc[7],pv,wb.y);
            }
        }
    }

    // epilogue: bias, store, fused stats
    float s[16], q[16];
    const int oz = tz0 + tz, oy = ty0 + ty;
    const int pix = oz*128 + oy;
    float* op = out + (size_t)osl*CHW;
#pragma unroll
    for (int t=0;t<8;t++){
        float x,y; unpack2(acc[t], x, y);
        float v0 = x + bias[2*t];
        float v1 = y + bias[2*t+1];
        op[(2*t)*HW   + pix] = v0;
        op[(2*t+1)*HW + pix] = v1;
        s[2*t]   = v0;  q[2*t]   = v0*v0;
        s[2*t+1] = v1;  q[2*t+1] = v1*v1;
    }
#pragma unroll
    for (int co=0;co<16;co++){
#pragma unroll
        for (int o=16;o>0;o>>=1){
            s[co] += __shfl_xor_sync(0xffffffffu, s[co], o);
            q[co] += __shfl_xor_sync(0xffffffffu, q[co], o);
        }
    }
    __syncthreads();
    if ((tid & 31) == 0){
        const int wd = tid >> 5;
#pragma unroll
        for (int co=0;co<16;co++){
            s_red[wd][co]    = s[co];
            s_red[wd][16+co] = q[co];
        }
    }
    __syncthreads();
    if (tid < 32){
        float t8 = 0.f;
#pragma unroll
        for (int wd=0; wd<8; wd++) t8 += s_red[wd][tid];
        t8 *= tp.mult[osl];
        if (tid < 16) atomicAdd(&stat_s[tid], t8);
        else          atomicAdd(&stat_q[tid-16], t8);
    }
}

// ---------------- stats zero ----------------
__global__ void zero_stats(){
    int i = threadIdx.x;
    if (i < 64){ g_sum[i]=0.f; g_sumsq[i]=0.f; }
}

// ---------------- fused final elementwise + forward projection ----------------
// final[sl] = relu( norm3(s3[sl]) + relu( norm1(s2[skm[sl]]) + V ) )
// out[c,0,z,u] = weighted slice sum at (z,y=u)
// out[c,1,z,u] = column sum over y of slice sel(u); u==0 sums only y=0..63
//   (reference fp32: x=+-3.9e-15 at uu=0, valid mask kills y in [64,127]).
__global__ __launch_bounds__(128) void forward_proj(
    const float* __restrict__ s3, const float* __restrict__ s2,
    const float* __restrict__ V, float* __restrict__ out)
{
    __shared__ float red[9][4];
    __shared__ float rs[9];
    const int c = blockIdx.x >> 7, z = blockIdx.x & 127;
    const int u = threadIdx.x;
    const int   skm[9]  = {0,1,2,2,2,2,2,3,4};
    const float mult[9] = {1.f,1.f,1.f,1.f,120.f,1.f,1.f,1.f,1.f};

    // inline stats finalize: bank1 (A2 output) and bank3 (B2 output)
    double sd1 = (double)g_sum[16+c], qd1 = (double)g_sumsq[16+c];
    double me1 = sd1/2097152.0;
    double i1d = 1.0/sqrt(qd1/2097152.0 - me1*me1 + 1e-5);
    const float i1 = (float)i1d, b1c = (float)(-me1*i1d);
    double sd3 = (double)g_sum[48+c], qd3 = (double)g_sumsq[48+c];
    double me3 = sd3/2097152.0;
    double i3d = 1.0/sqrt(qd3/2097152.0 - me3*me3 + 1e-5);
    const float i3 = (float)i3d, b3c = (float)(-me3*i3d);

    const int pix = z*128 + u;
    const float vb = V[c*HW + pix];

    float vals[9]; float s0 = 0.f;
#pragma unroll
    for (int sdx=0; sdx<9; sdx++){
        float t2 = s2[(size_t)(skm[sdx]*16 + c)*HW + pix];
        float sk = fmaxf(fmaf(t2, i1, b1c) + vb, 0.f);
        float t3 = s3[(size_t)(sdx*16 + c)*HW + pix];
        float fv = fmaxf(fmaf(t3, i3, b3c) + sk, 0.f);
        vals[sdx] = fv;
        s0 += mult[sdx]*fv;
    }
    out[(c*2+0)*HW + pix] = s0;

    const int lane = u & 31, wid = u >> 5;
#pragma unroll
    for (int sdx=0; sdx<9; sdx++){
        float v = vals[sdx];
#pragma unroll
        for (int o=16;o>0;o>>=1) v += __shfl_xor_sync(0xffffffffu, v, o);
        if (lane==0) red[sdx][wid]=v;
    }
    __syncthreads();
    if (u < 9) rs[u] = red[u][0]+red[u][1]+red[u][2]+red[u][3];
    __syncthreads();
    const int sl = (u<4) ? u : (u>123 ? u-119 : 4);
    float o1 = (u==0) ? (red[0][0]+red[0][1]) : rs[sl];
    out[(c*2+1)*HW + pix] = o1;
}

// ---------------- launch ----------------
extern "C" void kernel_launch(void* const* d_in, const int* in_sizes, int n_in,
                              void* d_out, int out_size)
{
    (void)in_sizes; (void)n_in; (void)out_size;
    const float* V    = (const float*)d_in[0];
    const float* w_a1 = (const float*)d_in[1];
    const float* b_a1 = (const float*)d_in[2];
    const float* w_a2 = (const float*)d_in[3];
    const float* b_a2 = (const float*)d_in[4];
    const float* w_b1 = (const float*)d_in[5];
    const float* b_b1 = (const float*)d_in[6];
    const float* w_b2 = (const float*)d_in[7];
    const float* b_b2 = (const float*)d_in[8];
    float* out = (float*)d_out;

    float *b1,*b2,*b3,*gsum,*gsq;
    cudaGetSymbolAddress((void**)&b1,    g_b1);
    cudaGetSymbolAddress((void**)&b2,    g_b2);
    cudaGetSymbolAddress((void**)&b3,    g_b3);
    cudaGetSymbolAddress((void**)&gsum,  g_sum);
    cudaGetSymbolAddress((void**)&gsq,   g_sumsq);

    // merged tap tables: (input slice, kx bitmask) per output slice
    Taps tA1 = {
        { {0,-1,-1},{0,-1,-1},{0,-1,-1} },
        { {6,0,0},{7,0,0},{3,0,0} },
        { 1.f,126.f,1.f }
    };
    Taps tA2 = {
        { {0,1,-1},{0,1,-1},{1,-1,-1},{1,2,-1},{1,2,-1} },
        { {2,4,0},{1,6,0},{7,0,0},{3,4,0},{1,2,0} },
        { 1.f,1.f,124.f,1.f,1.f }
    };
    Taps tB1 = {
        { {0,1,-1},{0,1,2},{1,2,-1},{2,-1,-1},{2,3,-1},{2,3,4},{3,4,-1} },
        { {2,4,0},{1,2,4},{1,6,0},{7,0,0},{3,4,0},{1,2,4},{1,2,0} },
        { 1.f,1.f,1.f,122.f,1.f,1.f,1.f }
    };
    Taps tB2 = {
        { {0,1,-1},{0,1,2},{1,2,3},{2,3,-1},{3,-1,-1},{3,4,-1},{3,4,5},{4,5,6},{5,6,-1} },
        { {2,4,0},{1,2,4},{1,2,4},{1,6,0},{7,0,0},{3,4,0},{1,2,4},{1,2,4},{1,2,0} },
        { 1.f,1.f,1.f,1.f,120.f,1.f,1.f,1.f,1.f }
    };

    zero_stats<<<1,64>>>();

    // A1: raw V (slice stride 0) -> b1 (3 slices), stats bank 0
    conv_stage<0><<<dim3(64,3),256>>>(V, 0, b1, w_a1, b_a1,
                                      nullptr, nullptr, nullptr,
                                      gsum+0, gsq+0, tA1);

    // A2: norm_relu(b1, bank0) -> b2 (5), stats bank 1
    conv_stage<1><<<dim3(64,5),256>>>(b1, CHW, b2, w_a2, b_a2,
                                      gsum+0, gsq+0, nullptr,
                                      gsum+16, gsq+16, tA2);

    // B1: relu(norm(b2, bank1) + V) -> b1 (7), stats bank 2
    conv_stage<2><<<dim3(64,7),256>>>(b2, CHW, b1, w_b1, b_b1,
                                      gsum+16, gsq+16, V,
                                      gsum+32, gsq+32, tB1);

    // B2: norm_relu(b1, bank2) -> b3 (9), stats bank 3
    conv_stage<1><<<dim3(64,9),256>>>(b1, CHW, b3, w_b2, b_b2,
                                      gsum+32, gsq+32, nullptr,
                                      gsum+48, gsq+48, tB2);

    // fused final norm+skip+relu + both projections (bank1+bank3 inline)
    forward_proj<<<16*128,128>>>(b3, b2, V, out);
}